// round 2
// baseline (speedup 1.0000x reference)
#include <cuda_runtime.h>
#include <math.h>

#define NN   100000
#define CONV 16
#define HIDD 1024
#define OUTD 256

// ---------------- device scratch (no allocations allowed) ----------------
__device__ int   g_deg[NN];
__device__ float g_dinv[NN];
__device__ float g_s1[NN];     // conv1 accumulator
__device__ float g_xn[NN];     // x[i]*dinv[i]
__device__ float g_s2[NN];     // conv2 accumulator
__device__ float g_hhn[NN];    // hh[i]*dinv[i]
__device__ float g_v[NN];      // final node scalar
__device__ float g_z[HIDD];    // hidden layer

__device__ __forceinline__ float lrelu(float x) {
    return x >= 0.0f ? x : 0.01f * x;
}

// ---------------- kernels ----------------
__global__ void k_zero_deg() {
    int i = blockIdx.x * blockDim.x + threadIdx.x;
    if (i < NN) g_deg[i] = 0;
}

__global__ void k_deg(const int* __restrict__ dst, int E) {
    int e = blockIdx.x * blockDim.x + threadIdx.x;
    if (e < E) {
        int d = __ldg(&dst[e]);
        if ((unsigned)d < (unsigned)NN) atomicAdd(&g_deg[d], 1);
    }
}

__global__ void k_node1(const float* __restrict__ x) {
    int i = blockIdx.x * blockDim.x + threadIdx.x;
    if (i < NN) {
        // self-loop adds 1 to degree -> always >= 1
        float dinv = rsqrtf((float)g_deg[i] + 1.0f);
        g_dinv[i] = dinv;
        float xn = x[i] * dinv;
        g_xn[i] = xn;
        g_s1[i] = xn * dinv;   // self-loop contribution (assignment, no pre-zero)
    }
}

__global__ void k_scatter1(const int* __restrict__ src,
                           const int* __restrict__ dst, int E) {
    int e = blockIdx.x * blockDim.x + threadIdx.x;
    if (e < E) {
        int s = __ldg(&src[e]);
        int d = __ldg(&dst[e]);
        if ((unsigned)s < (unsigned)NN && (unsigned)d < (unsigned)NN)
            atomicAdd(&g_s1[d], g_xn[s]);
    }
}

__global__ void k_node2(const float* __restrict__ W1c,
                        const float* __restrict__ b1c,
                        const float* __restrict__ W2c) {
    int i = blockIdx.x * blockDim.x + threadIdx.x;
    if (i < NN) {
        float dinv = g_dinv[i];
        float a = dinv * g_s1[i];          // conv1 output scalar factor
        float hh = 0.0f;
#pragma unroll
        for (int c = 0; c < CONV; c++) {
            float t = fmaf(a, __ldg(&W1c[c]), __ldg(&b1c[c]));
            t = lrelu(t);
            hh = fmaf(t, __ldg(&W2c[c]), hh);
        }
        float hn = hh * dinv;
        g_hhn[i] = hn;
        g_s2[i] = hn * dinv;               // self-loop contribution
    }
}

__global__ void k_scatter2(const int* __restrict__ src,
                           const int* __restrict__ dst, int E) {
    int e = blockIdx.x * blockDim.x + threadIdx.x;
    if (e < E) {
        int s = __ldg(&src[e]);
        int d = __ldg(&dst[e]);
        if ((unsigned)s < (unsigned)NN && (unsigned)d < (unsigned)NN)
            atomicAdd(&g_s2[d], g_hhn[s]);
    }
}

__global__ void k_node3(const float* __restrict__ b2c) {
    int i = blockIdx.x * blockDim.x + threadIdx.x;
    if (i < NN) {
        float t = g_dinv[i] * g_s2[i] + __ldg(&b2c[0]);
        g_v[i] = lrelu(t);
    }
}

// GEMV: z[h] = lrelu( dot(Wf1[h,:], v) + bf1[h] ), one block per row, float4 loads.
__global__ void k_gemv(const float* __restrict__ Wf1,
                       const float* __restrict__ bf1) {
    const int h = blockIdx.x;
    const int tid = threadIdx.x;
    const float4* __restrict__ row = (const float4*)(Wf1 + (size_t)h * NN);
    const float4* __restrict__ vv  = (const float4*)g_v;
    float s = 0.0f;
    const int n4 = NN / 4;  // 25000
    for (int i = tid; i < n4; i += blockDim.x) {
        float4 w = __ldg(&row[i]);
        float4 x = vv[i];
        s += w.x * x.x + w.y * x.y + w.z * x.z + w.w * x.w;
    }
    // warp reduce
#pragma unroll
    for (int o = 16; o > 0; o >>= 1)
        s += __shfl_down_sync(0xFFFFFFFFu, s, o);
    __shared__ float red[32];
    int lane = tid & 31, wid = tid >> 5;
    if (lane == 0) red[wid] = s;
    __syncthreads();
    if (wid == 0) {
        s = (lane < (blockDim.x >> 5)) ? red[lane] : 0.0f;
#pragma unroll
        for (int o = 16; o > 0; o >>= 1)
            s += __shfl_down_sync(0xFFFFFFFFu, s, o);
        if (lane == 0) {
            g_z[h] = lrelu(s + __ldg(&bf1[h]));
        }
    }
}

// out[o] = log_softmax( Wf2 @ z + bf2 )[o]; one block of 256 threads.
__global__ void k_final(const float* __restrict__ Wf2,
                        const float* __restrict__ bf2,
                        float* __restrict__ out) {
    __shared__ float zs[HIDD];
    __shared__ float red[OUTD];
    const int t = threadIdx.x;
    for (int i = t; i < HIDD; i += OUTD) zs[i] = g_z[i];
    __syncthreads();

    const float* __restrict__ row = Wf2 + (size_t)t * HIDD;
    float s = 0.0f;
#pragma unroll 8
    for (int h = 0; h < HIDD; h++) s = fmaf(__ldg(&row[h]), zs[h], s);
    s += __ldg(&bf2[t]);

    // max reduce
    red[t] = s;
    __syncthreads();
#pragma unroll
    for (int o = OUTD / 2; o > 0; o >>= 1) {
        if (t < o) red[t] = fmaxf(red[t], red[t + o]);
        __syncthreads();
    }
    float mx = red[0];
    __syncthreads();

    // sum(exp) reduce
    red[t] = expf(s - mx);
    __syncthreads();
#pragma unroll
    for (int o = OUTD / 2; o > 0; o >>= 1) {
        if (t < o) red[t] += red[t + o];
        __syncthreads();
    }
    float lse = mx + logf(red[0]);
    out[t] = s - lse;
}

// ---------------- launch ----------------
extern "C" void kernel_launch(void* const* d_in, const int* in_sizes, int n_in,
                              void* d_out, int out_size) {
    const float* x   = (const float*)d_in[0];
    const int*   ei  = (const int*)d_in[1];     // int32: jax downcasts int64 w/o x64
    const float* W1c = (const float*)d_in[2];
    const float* b1c = (const float*)d_in[3];
    const float* W2c = (const float*)d_in[4];
    const float* b2c = (const float*)d_in[5];
    const float* Wf1 = (const float*)d_in[6];
    const float* bf1 = (const float*)d_in[7];
    const float* Wf2 = (const float*)d_in[8];
    const float* bf2 = (const float*)d_in[9];
    float* out = (float*)d_out;

    const int E = in_sizes[1] / 2;
    const int* src = ei;
    const int* dst = ei + E;

    const int TB = 256;
    const int nb_node = (NN + TB - 1) / TB;
    const int nb_edge = (E + TB - 1) / TB;

    k_zero_deg<<<nb_node, TB>>>();
    k_deg<<<nb_edge, TB>>>(dst, E);
    k_node1<<<nb_node, TB>>>(x);
    k_scatter1<<<nb_edge, TB>>>(src, dst, E);
    k_node2<<<nb_node, TB>>>(W1c, b1c, W2c);
    k_scatter2<<<nb_edge, TB>>>(src, dst, E);
    k_node3<<<nb_node, TB>>>(b2c);
    k_gemv<<<HIDD, TB>>>(Wf1, bf1);
    k_final<<<1, OUTD>>>(Wf2, bf2, out);
}

// round 3
// speedup vs baseline: 1.6050x; 1.6050x over previous
#include <cuda_runtime.h>
#include <math.h>

#define NN   100000
#define CONV 16
#define HIDD 1024
#define OUTD 256

// ---------------- device scratch (no allocations allowed) ----------------
__device__ int   g_deg[NN];
__device__ float g_dinv[NN];
__device__ float g_s1[NN];     // conv1 accumulator
__device__ float g_xn[NN];     // x[i]*dinv[i]
__device__ float g_s2[NN];     // conv2 accumulator
__device__ float g_hhn[NN];    // hh[i]*dinv[i]
__device__ float g_v[NN];      // final node scalar
__device__ float g_z[HIDD];    // hidden layer (post-lrelu)
__device__ float g_logits[OUTD];

__device__ __forceinline__ float lrelu(float x) {
    return x >= 0.0f ? x : 0.01f * x;
}

// ---------------- node kernels ----------------
__global__ void k_zero_deg() {
    int i = blockIdx.x * blockDim.x + threadIdx.x;
    if (i < NN) g_deg[i] = 0;
}

__global__ void k_node1(const float* __restrict__ x) {
    int i = blockIdx.x * blockDim.x + threadIdx.x;
    if (i < NN) {
        float dinv = rsqrtf((float)g_deg[i] + 1.0f);  // +1 = self-loop
        g_dinv[i] = dinv;
        float xn = x[i] * dinv;
        g_xn[i] = xn;
        g_s1[i] = xn * dinv;   // self-loop contribution
    }
}

__global__ void k_node2(const float* __restrict__ W1c,
                        const float* __restrict__ b1c,
                        const float* __restrict__ W2c) {
    int i = blockIdx.x * blockDim.x + threadIdx.x;
    if (i < NN) {
        float dinv = g_dinv[i];
        float a = dinv * g_s1[i];
        float hh = 0.0f;
#pragma unroll
        for (int c = 0; c < CONV; c++) {
            float t = fmaf(a, __ldg(&W1c[c]), __ldg(&b1c[c]));
            t = lrelu(t);
            hh = fmaf(t, __ldg(&W2c[c]), hh);
        }
        float hn = hh * dinv;
        g_hhn[i] = hn;
        g_s2[i] = hn * dinv;   // self-loop contribution
    }
}

__global__ void k_node3(const float* __restrict__ b2c) {
    int i = blockIdx.x * blockDim.x + threadIdx.x;
    if (i < NN) {
        float t = g_dinv[i] * g_s2[i] + __ldg(&b2c[0]);
        g_v[i] = lrelu(t);
    }
}

// ---------------- edge kernels: 4 edges per thread via int4 ----------------
__global__ void k_deg(const int4* __restrict__ dst4, int E4) {
    int e = blockIdx.x * blockDim.x + threadIdx.x;
    if (e < E4) {
        int4 d = __ldg(&dst4[e]);
        if ((unsigned)d.x < (unsigned)NN) atomicAdd(&g_deg[d.x], 1);
        if ((unsigned)d.y < (unsigned)NN) atomicAdd(&g_deg[d.y], 1);
        if ((unsigned)d.z < (unsigned)NN) atomicAdd(&g_deg[d.z], 1);
        if ((unsigned)d.w < (unsigned)NN) atomicAdd(&g_deg[d.w], 1);
    }
}

__global__ void k_scatter1(const int4* __restrict__ src4,
                           const int4* __restrict__ dst4, int E4) {
    int e = blockIdx.x * blockDim.x + threadIdx.x;
    if (e < E4) {
        int4 s = __ldg(&src4[e]);
        int4 d = __ldg(&dst4[e]);
        float vx = g_xn[s.x], vy = g_xn[s.y], vz = g_xn[s.z], vw = g_xn[s.w];
        if ((unsigned)d.x < (unsigned)NN) atomicAdd(&g_s1[d.x], vx);
        if ((unsigned)d.y < (unsigned)NN) atomicAdd(&g_s1[d.y], vy);
        if ((unsigned)d.z < (unsigned)NN) atomicAdd(&g_s1[d.z], vz);
        if ((unsigned)d.w < (unsigned)NN) atomicAdd(&g_s1[d.w], vw);
    }
}

__global__ void k_scatter2(const int4* __restrict__ src4,
                           const int4* __restrict__ dst4, int E4) {
    int e = blockIdx.x * blockDim.x + threadIdx.x;
    if (e < E4) {
        int4 s = __ldg(&src4[e]);
        int4 d = __ldg(&dst4[e]);
        float vx = g_hhn[s.x], vy = g_hhn[s.y], vz = g_hhn[s.z], vw = g_hhn[s.w];
        if ((unsigned)d.x < (unsigned)NN) atomicAdd(&g_s2[d.x], vx);
        if ((unsigned)d.y < (unsigned)NN) atomicAdd(&g_s2[d.y], vy);
        if ((unsigned)d.z < (unsigned)NN) atomicAdd(&g_s2[d.z], vz);
        if ((unsigned)d.w < (unsigned)NN) atomicAdd(&g_s2[d.w], vw);
    }
}

// ---------------- GEMV: z[h] = lrelu(dot(Wf1[h,:], v) + bf1[h]) ----------------
// One block per row, 256 threads, 4-way ILP (4 independent accumulators).
__global__ void k_gemv(const float* __restrict__ Wf1,
                       const float* __restrict__ bf1) {
    const int h = blockIdx.x;
    const int tid = threadIdx.x;
    const float4* __restrict__ row = (const float4*)(Wf1 + (size_t)h * NN);
    const float4* __restrict__ vv  = (const float4*)g_v;
    const int n4 = NN / 4;          // 25000
    const int nfull = (n4 / 1024) * 1024;  // 24576

    float s0 = 0.f, s1 = 0.f, s2 = 0.f, s3 = 0.f;
    for (int i = tid; i < nfull; i += 1024) {
        float4 w0 = __ldg(&row[i]);
        float4 w1 = __ldg(&row[i + 256]);
        float4 w2 = __ldg(&row[i + 512]);
        float4 w3 = __ldg(&row[i + 768]);
        float4 x0 = vv[i];
        float4 x1 = vv[i + 256];
        float4 x2 = vv[i + 512];
        float4 x3 = vv[i + 768];
        s0 += w0.x*x0.x + w0.y*x0.y + w0.z*x0.z + w0.w*x0.w;
        s1 += w1.x*x1.x + w1.y*x1.y + w1.z*x1.z + w1.w*x1.w;
        s2 += w2.x*x2.x + w2.y*x2.y + w2.z*x2.z + w2.w*x2.w;
        s3 += w3.x*x3.x + w3.y*x3.y + w3.z*x3.z + w3.w*x3.w;
    }
    for (int i = nfull + tid; i < n4; i += 256) {
        float4 w = __ldg(&row[i]);
        float4 x = vv[i];
        s0 += w.x*x.x + w.y*x.y + w.z*x.z + w.w*x.w;
    }
    float s = (s0 + s1) + (s2 + s3);

#pragma unroll
    for (int o = 16; o > 0; o >>= 1)
        s += __shfl_down_sync(0xFFFFFFFFu, s, o);
    __shared__ float red[8];
    int lane = tid & 31, wid = tid >> 5;
    if (lane == 0) red[wid] = s;
    __syncthreads();
    if (wid == 0) {
        s = (lane < 8) ? red[lane] : 0.0f;
#pragma unroll
        for (int o = 4; o > 0; o >>= 1)
            s += __shfl_down_sync(0xFFFFFFFFu, s, o);
        if (lane == 0) g_z[h] = lrelu(s + __ldg(&bf1[h]));
    }
}

// ---------------- FC2: one block per output row ----------------
__global__ void k_fc2(const float* __restrict__ Wf2,
                      const float* __restrict__ bf2) {
    const int o = blockIdx.x;          // 0..255
    const int tid = threadIdx.x;       // 128 threads
    const float4* __restrict__ row = (const float4*)(Wf2 + (size_t)o * HIDD);
    const float4* __restrict__ zz  = (const float4*)g_z;
    float s = 0.0f;
#pragma unroll
    for (int i = tid; i < HIDD / 4; i += 128) {   // 2 iterations
        float4 w = __ldg(&row[i]);
        float4 z = zz[i];
        s += w.x*z.x + w.y*z.y + w.z*z.z + w.w*z.w;
    }
#pragma unroll
    for (int off = 16; off > 0; off >>= 1)
        s += __shfl_down_sync(0xFFFFFFFFu, s, off);
    __shared__ float red[4];
    int lane = tid & 31, wid = tid >> 5;
    if (lane == 0) red[wid] = s;
    __syncthreads();
    if (tid == 0) {
        float t = red[0] + red[1] + red[2] + red[3];
        g_logits[o] = t + __ldg(&bf2[o]);
    }
}

// ---------------- log_softmax over 256 logits ----------------
__global__ void k_logsoftmax(float* __restrict__ out) {
    __shared__ float red[OUTD];
    const int t = threadIdx.x;
    float s = g_logits[t];

    red[t] = s;
    __syncthreads();
#pragma unroll
    for (int o = OUTD / 2; o > 0; o >>= 1) {
        if (t < o) red[t] = fmaxf(red[t], red[t + o]);
        __syncthreads();
    }
    float mx = red[0];
    __syncthreads();

    red[t] = expf(s - mx);
    __syncthreads();
#pragma unroll
    for (int o = OUTD / 2; o > 0; o >>= 1) {
        if (t < o) red[t] += red[t + o];
        __syncthreads();
    }
    float lse = mx + logf(red[0]);
    out[t] = s - lse;
}

// ---------------- launch ----------------
extern "C" void kernel_launch(void* const* d_in, const int* in_sizes, int n_in,
                              void* d_out, int out_size) {
    const float* x   = (const float*)d_in[0];
    const int*   ei  = (const int*)d_in[1];     // int32 (jax downcast)
    const float* W1c = (const float*)d_in[2];
    const float* b1c = (const float*)d_in[3];
    const float* W2c = (const float*)d_in[4];
    const float* b2c = (const float*)d_in[5];
    const float* Wf1 = (const float*)d_in[6];
    const float* bf1 = (const float*)d_in[7];
    const float* Wf2 = (const float*)d_in[8];
    const float* bf2 = (const float*)d_in[9];
    float* out = (float*)d_out;

    const int E = in_sizes[1] / 2;              // 3,200,000
    const int E4 = E / 4;                       // 800,000 (exact)
    const int4* src4 = (const int4*)ei;         // 16B-aligned
    const int4* dst4 = (const int4*)(ei + E);   // E*4 bytes = 16B multiple

    const int TB = 256;
    const int nb_node  = (NN + TB - 1) / TB;
    const int nb_edge4 = (E4 + TB - 1) / TB;

    k_zero_deg<<<nb_node, TB>>>();
    k_deg<<<nb_edge4, TB>>>(dst4, E4);
    k_node1<<<nb_node, TB>>>(x);
    k_scatter1<<<nb_edge4, TB>>>(src4, dst4, E4);
    k_node2<<<nb_node, TB>>>(W1c, b1c, W2c);
    k_scatter2<<<nb_edge4, TB>>>(src4, dst4, E4);
    k_node3<<<nb_node, TB>>>(b2c);
    k_gemv<<<HIDD, TB>>>(Wf1, bf1);
    k_fc2<<<OUTD, 128>>>(Wf2, bf2);
    k_logsoftmax<<<1, OUTD>>>(out);
}

// round 5
// speedup vs baseline: 1.7202x; 1.0717x over previous
#include <cuda_runtime.h>
#include <math.h>

#define NN   100000
#define CONV 16
#define HIDD 1024
#define OUTD 256

// ---------------- device scratch (no allocations allowed) ----------------
__device__ float g_degf[NN];
__device__ float g_dinv[NN];
__device__ float g_s1[NN];     // conv1 accumulator
__device__ float g_xn[NN];     // x[i]*dinv[i]
__device__ float g_s2[NN];     // conv2 accumulator
__device__ float g_hhn[NN];    // hh[i]*dinv[i]
__device__ float g_v[NN];      // final node scalar
__device__ float g_z[HIDD];    // hidden layer (post-lrelu)
__device__ float g_logits[OUTD];

__device__ __forceinline__ float lrelu(float x) {
    return x >= 0.0f ? x : 0.01f * x;
}

// ---------------- node kernels ----------------
__global__ void k_zero_deg() {
    int i = blockIdx.x * blockDim.x + threadIdx.x;
    if (i < NN) g_degf[i] = 0.0f;
}

__global__ void k_node1(const float* __restrict__ x) {
    int i = blockIdx.x * blockDim.x + threadIdx.x;
    if (i < NN) {
        float dinv = rsqrtf(g_degf[i] + 1.0f);  // +1 = self-loop
        g_dinv[i] = dinv;
        float xn = x[i] * dinv;
        g_xn[i] = xn;
        g_s1[i] = xn * dinv;   // self-loop contribution
    }
}

__global__ void k_node2(const float* __restrict__ W1c,
                        const float* __restrict__ b1c,
                        const float* __restrict__ W2c) {
    int i = blockIdx.x * blockDim.x + threadIdx.x;
    if (i < NN) {
        float dinv = g_dinv[i];
        float a = dinv * g_s1[i];
        float hh = 0.0f;
#pragma unroll
        for (int c = 0; c < CONV; c++) {
            float t = fmaf(a, __ldg(&W1c[c]), __ldg(&b1c[c]));
            t = lrelu(t);
            hh = fmaf(t, __ldg(&W2c[c]), hh);
        }
        float hn = hh * dinv;
        g_hhn[i] = hn;
        g_s2[i] = hn * dinv;   // self-loop contribution
    }
}

__global__ void k_node3(const float* __restrict__ b2c) {
    int i = blockIdx.x * blockDim.x + threadIdx.x;
    if (i < NN) {
        float t = g_dinv[i] * g_s2[i] + __ldg(&b2c[0]);
        g_v[i] = lrelu(t);
    }
}

// ---------------- edge kernels: 8 edges per thread (2 x int4) ----------------
// E4 is guaranteed even (E = 3.2M -> E4 = 800K), so each thread takes pairs.
__global__ void k_deg(const int4* __restrict__ dst4, int E4) {
    int t = blockIdx.x * blockDim.x + threadIdx.x;
    int e = t * 2;
    if (e < E4) {
        int4 d0 = __ldg(&dst4[e]);
        int4 d1 = __ldg(&dst4[e + 1]);
        if ((unsigned)d0.x < (unsigned)NN) atomicAdd(&g_degf[d0.x], 1.0f);
        if ((unsigned)d0.y < (unsigned)NN) atomicAdd(&g_degf[d0.y], 1.0f);
        if ((unsigned)d0.z < (unsigned)NN) atomicAdd(&g_degf[d0.z], 1.0f);
        if ((unsigned)d0.w < (unsigned)NN) atomicAdd(&g_degf[d0.w], 1.0f);
        if ((unsigned)d1.x < (unsigned)NN) atomicAdd(&g_degf[d1.x], 1.0f);
        if ((unsigned)d1.y < (unsigned)NN) atomicAdd(&g_degf[d1.y], 1.0f);
        if ((unsigned)d1.z < (unsigned)NN) atomicAdd(&g_degf[d1.z], 1.0f);
        if ((unsigned)d1.w < (unsigned)NN) atomicAdd(&g_degf[d1.w], 1.0f);
    }
}

__global__ void k_scatter1(const int4* __restrict__ src4,
                           const int4* __restrict__ dst4, int E4) {
    int t = blockIdx.x * blockDim.x + threadIdx.x;
    int e = t * 2;
    if (e < E4) {
        int4 s0 = __ldg(&src4[e]);
        int4 s1 = __ldg(&src4[e + 1]);
        int4 d0 = __ldg(&dst4[e]);
        int4 d1 = __ldg(&dst4[e + 1]);
        float v0 = g_xn[s0.x], v1 = g_xn[s0.y], v2 = g_xn[s0.z], v3 = g_xn[s0.w];
        float v4 = g_xn[s1.x], v5 = g_xn[s1.y], v6 = g_xn[s1.z], v7 = g_xn[s1.w];
        if ((unsigned)d0.x < (unsigned)NN) atomicAdd(&g_s1[d0.x], v0);
        if ((unsigned)d0.y < (unsigned)NN) atomicAdd(&g_s1[d0.y], v1);
        if ((unsigned)d0.z < (unsigned)NN) atomicAdd(&g_s1[d0.z], v2);
        if ((unsigned)d0.w < (unsigned)NN) atomicAdd(&g_s1[d0.w], v3);
        if ((unsigned)d1.x < (unsigned)NN) atomicAdd(&g_s1[d1.x], v4);
        if ((unsigned)d1.y < (unsigned)NN) atomicAdd(&g_s1[d1.y], v5);
        if ((unsigned)d1.z < (unsigned)NN) atomicAdd(&g_s1[d1.z], v6);
        if ((unsigned)d1.w < (unsigned)NN) atomicAdd(&g_s1[d1.w], v7);
    }
}

__global__ void k_scatter2(const int4* __restrict__ src4,
                           const int4* __restrict__ dst4, int E4) {
    int t = blockIdx.x * blockDim.x + threadIdx.x;
    int e = t * 2;
    if (e < E4) {
        int4 s0 = __ldg(&src4[e]);
        int4 s1 = __ldg(&src4[e + 1]);
        int4 d0 = __ldg(&dst4[e]);
        int4 d1 = __ldg(&dst4[e + 1]);
        float v0 = g_hhn[s0.x], v1 = g_hhn[s0.y], v2 = g_hhn[s0.z], v3 = g_hhn[s0.w];
        float v4 = g_hhn[s1.x], v5 = g_hhn[s1.y], v6 = g_hhn[s1.z], v7 = g_hhn[s1.w];
        if ((unsigned)d0.x < (unsigned)NN) atomicAdd(&g_s2[d0.x], v0);
        if ((unsigned)d0.y < (unsigned)NN) atomicAdd(&g_s2[d0.y], v1);
        if ((unsigned)d0.z < (unsigned)NN) atomicAdd(&g_s2[d0.z], v2);
        if ((unsigned)d0.w < (unsigned)NN) atomicAdd(&g_s2[d0.w], v3);
        if ((unsigned)d1.x < (unsigned)NN) atomicAdd(&g_s2[d1.x], v4);
        if ((unsigned)d1.y < (unsigned)NN) atomicAdd(&g_s2[d1.y], v5);
        if ((unsigned)d1.z < (unsigned)NN) atomicAdd(&g_s2[d1.z], v6);
        if ((unsigned)d1.w < (unsigned)NN) atomicAdd(&g_s2[d1.w], v7);
    }
}

// ---------------- GEMV: 2 rows per block, v4 shared across rows ----------------
__global__ void k_gemv(const float* __restrict__ Wf1,
                       const float* __restrict__ bf1) {
    const int r0 = blockIdx.x * 2;
    const int tid = threadIdx.x;
    const float4* __restrict__ rowA = (const float4*)(Wf1 + (size_t)r0 * NN);
    const float4* __restrict__ rowB = (const float4*)(Wf1 + (size_t)(r0 + 1) * NN);
    const float4* __restrict__ vv   = (const float4*)g_v;
    const int n4 = NN / 4;                 // 25000
    const int nfull = (n4 / 512) * 512;    // 24576

    float a0 = 0.f, a1 = 0.f, b0 = 0.f, b1 = 0.f;
    for (int i = tid; i < nfull; i += 512) {
        float4 x0 = vv[i];
        float4 x1 = vv[i + 256];
        float4 wA0 = __ldg(&rowA[i]);
        float4 wA1 = __ldg(&rowA[i + 256]);
        float4 wB0 = __ldg(&rowB[i]);
        float4 wB1 = __ldg(&rowB[i + 256]);
        a0 += wA0.x*x0.x + wA0.y*x0.y + wA0.z*x0.z + wA0.w*x0.w;
        a1 += wA1.x*x1.x + wA1.y*x1.y + wA1.z*x1.z + wA1.w*x1.w;
        b0 += wB0.x*x0.x + wB0.y*x0.y + wB0.z*x0.z + wB0.w*x0.w;
        b1 += wB1.x*x1.x + wB1.y*x1.y + wB1.z*x1.z + wB1.w*x1.w;
    }
    for (int i = nfull + tid; i < n4; i += 256) {
        float4 x = vv[i];
        float4 wA = __ldg(&rowA[i]);
        float4 wB = __ldg(&rowB[i]);
        a0 += wA.x*x.x + wA.y*x.y + wA.z*x.z + wA.w*x.w;
        b0 += wB.x*x.x + wB.y*x.y + wB.z*x.z + wB.w*x.w;
    }
    float sa = a0 + a1;
    float sb = b0 + b1;

#pragma unroll
    for (int o = 16; o > 0; o >>= 1) {
        sa += __shfl_down_sync(0xFFFFFFFFu, sa, o);
        sb += __shfl_down_sync(0xFFFFFFFFu, sb, o);
    }
    __shared__ float redA[8], redB[8];
    int lane = tid & 31, wid = tid >> 5;
    if (lane == 0) { redA[wid] = sa; redB[wid] = sb; }
    __syncthreads();
    if (wid == 0) {
        sa = (lane < 8) ? redA[lane] : 0.0f;
        sb = (lane < 8) ? redB[lane] : 0.0f;
#pragma unroll
        for (int o = 4; o > 0; o >>= 1) {
            sa += __shfl_down_sync(0xFFFFFFFFu, sa, o);
            sb += __shfl_down_sync(0xFFFFFFFFu, sb, o);
        }
        if (lane == 0) {
            g_z[r0]     = lrelu(sa + __ldg(&bf1[r0]));
            g_z[r0 + 1] = lrelu(sb + __ldg(&bf1[r0 + 1]));
        }
    }
}

// ---------------- FC2: one block per output row ----------------
__global__ void k_fc2(const float* __restrict__ Wf2,
                      const float* __restrict__ bf2) {
    const int o = blockIdx.x;          // 0..255
    const int tid = threadIdx.x;       // 128 threads
    const float4* __restrict__ row = (const float4*)(Wf2 + (size_t)o * HIDD);
    const float4* __restrict__ zz  = (const float4*)g_z;
    float s = 0.0f;
#pragma unroll
    for (int i = tid; i < HIDD / 4; i += 128) {   // 2 iterations
        float4 w = __ldg(&row[i]);
        float4 z = zz[i];
        s += w.x*z.x + w.y*z.y + w.z*z.z + w.w*z.w;
    }
#pragma unroll
    for (int off = 16; off > 0; off >>= 1)
        s += __shfl_down_sync(0xFFFFFFFFu, s, off);
    __shared__ float red[4];
    int lane = tid & 31, wid = tid >> 5;
    if (lane == 0) red[wid] = s;
    __syncthreads();
    if (tid == 0) {
        float t = red[0] + red[1] + red[2] + red[3];
        g_logits[o] = t + __ldg(&bf2[o]);
    }
}

// ---------------- log_softmax over 256 logits ----------------
__global__ void k_logsoftmax(float* __restrict__ out) {
    __shared__ float red[OUTD];
    const int t = threadIdx.x;
    float s = g_logits[t];

    red[t] = s;
    __syncthreads();
#pragma unroll
    for (int o = OUTD / 2; o > 0; o >>= 1) {
        if (t < o) red[t] = fmaxf(red[t], red[t + o]);
        __syncthreads();
    }
    float mx = red[0];
    __syncthreads();

    red[t] = expf(s - mx);
    __syncthreads();
#pragma unroll
    for (int o = OUTD / 2; o > 0; o >>= 1) {
        if (t < o) red[t] += red[t + o];
        __syncthreads();
    }
    float lse = mx + logf(red[0]);
    out[t] = s - lse;
}

// ---------------- launch ----------------
extern "C" void kernel_launch(void* const* d_in, const int* in_sizes, int n_in,
                              void* d_out, int out_size) {
    const float* x   = (const float*)d_in[0];
    const int*   ei  = (const int*)d_in[1];     // int32 (jax downcast)
    const float* W1c = (const float*)d_in[2];
    const float* b1c = (const float*)d_in[3];
    const float* W2c = (const float*)d_in[4];
    const float* b2c = (const float*)d_in[5];
    const float* Wf1 = (const float*)d_in[6];
    const float* bf1 = (const float*)d_in[7];
    const float* Wf2 = (const float*)d_in[8];
    const float* bf2 = (const float*)d_in[9];
    float* out = (float*)d_out;

    const int E = in_sizes[1] / 2;              // 3,200,000
    const int E4 = E / 4;                       // 800,000 (exact, even)
    const int4* src4 = (const int4*)ei;
    const int4* dst4 = (const int4*)(ei + E);

    const int TB = 256;
    const int nb_node  = (NN + TB - 1) / TB;
    const int nb_edge8 = (E4 / 2 + TB - 1) / TB;   // 8 edges per thread

    k_zero_deg<<<nb_node, TB>>>();
    k_deg<<<nb_edge8, TB>>>(dst4, E4);
    k_node1<<<nb_node, TB>>>(x);
    k_scatter1<<<nb_edge8, TB>>>(src4, dst4, E4);
    k_node2<<<nb_node, TB>>>(W1c, b1c, W2c);
    k_scatter2<<<nb_edge8, TB>>>(src4, dst4, E4);
    k_node3<<<nb_node, TB>>>(b2c);
    k_gemv<<<HIDD / 2, TB>>>(Wf1, bf1);
    k_fc2<<<OUTD, 128>>>(Wf2, bf2);
    k_logsoftmax<<<1, OUTD>>>(out);
}

// round 7
// speedup vs baseline: 1.8185x; 1.0571x over previous
#include <cuda_runtime.h>
#include <cuda_fp16.h>
#include <math.h>

#define NN   100000
#define CONV 16
#define HIDD 1024
#define OUTD 256

// ---------------- device scratch (no allocations allowed) ----------------
__device__ float  g_degf[NN];
__device__ float  g_dinv[NN];
__device__ float  g_s1[NN];      // conv1 accumulator (fp32 atomics)
__device__ __half g_xnh[NN];     // x[i]*dinv[i] as fp16 (L1-resident gather array)
__device__ float  g_s2[NN];      // conv2 accumulator
__device__ __half g_hhnh[NN];    // hh[i]*dinv[i] as fp16
__device__ float  g_v[NN];       // final node scalar
__device__ float  g_z[HIDD];     // hidden layer (post-lrelu)
__device__ float  g_logits[OUTD];

__device__ __forceinline__ float lrelu(float x) {
    return x >= 0.0f ? x : 0.01f * x;
}

// ---------------- node kernels ----------------
__global__ void k_node1(const float* __restrict__ x) {
    int i = blockIdx.x * blockDim.x + threadIdx.x;
    if (i < NN) {
        float dinv = rsqrtf(g_degf[i] + 1.0f);  // +1 = self-loop
        g_dinv[i] = dinv;
        float xn = x[i] * dinv;
        g_xnh[i] = __float2half(xn);
        g_s1[i] = xn * dinv;   // self-loop contribution (fp32, exact)
    }
}

__global__ void k_node2(const float* __restrict__ W1c,
                        const float* __restrict__ b1c,
                        const float* __restrict__ W2c) {
    int i = blockIdx.x * blockDim.x + threadIdx.x;
    if (i < NN) {
        float dinv = g_dinv[i];
        float a = dinv * g_s1[i];
        float hh = 0.0f;
#pragma unroll
        for (int c = 0; c < CONV; c++) {
            float t = fmaf(a, __ldg(&W1c[c]), __ldg(&b1c[c]));
            t = lrelu(t);
            hh = fmaf(t, __ldg(&W2c[c]), hh);
        }
        float hn = hh * dinv;
        g_hhnh[i] = __float2half(hn);
        g_s2[i] = hn * dinv;   // self-loop contribution (fp32)
    }
}

__global__ void k_node3(const float* __restrict__ b2c) {
    int i = blockIdx.x * blockDim.x + threadIdx.x;
    if (i < NN) {
        float t = g_dinv[i] * g_s2[i] + __ldg(&b2c[0]);
        g_v[i] = lrelu(t);
    }
}

// ---------------- edge kernels: 4 edges per thread via int4 ----------------
__global__ void k_deg(const int4* __restrict__ dst4, int E4) {
    int e = blockIdx.x * blockDim.x + threadIdx.x;
    if (e < E4) {
        int4 d = __ldg(&dst4[e]);
        if ((unsigned)d.x < (unsigned)NN) atomicAdd(&g_degf[d.x], 1.0f);
        if ((unsigned)d.y < (unsigned)NN) atomicAdd(&g_degf[d.y], 1.0f);
        if ((unsigned)d.z < (unsigned)NN) atomicAdd(&g_degf[d.z], 1.0f);
        if ((unsigned)d.w < (unsigned)NN) atomicAdd(&g_degf[d.w], 1.0f);
    }
}

__global__ void k_scatter1(const int4* __restrict__ src4,
                           const int4* __restrict__ dst4, int E4) {
    int e = blockIdx.x * blockDim.x + threadIdx.x;
    if (e < E4) {
        int4 s = __ldg(&src4[e]);
        int4 d = __ldg(&dst4[e]);
        float vx = __half2float(g_xnh[s.x]);
        float vy = __half2float(g_xnh[s.y]);
        float vz = __half2float(g_xnh[s.z]);
        float vw = __half2float(g_xnh[s.w]);
        if ((unsigned)d.x < (unsigned)NN) atomicAdd(&g_s1[d.x], vx);
        if ((unsigned)d.y < (unsigned)NN) atomicAdd(&g_s1[d.y], vy);
        if ((unsigned)d.z < (unsigned)NN) atomicAdd(&g_s1[d.z], vz);
        if ((unsigned)d.w < (unsigned)NN) atomicAdd(&g_s1[d.w], vw);
    }
}

__global__ void k_scatter2(const int4* __restrict__ src4,
                           const int4* __restrict__ dst4, int E4) {
    int e = blockIdx.x * blockDim.x + threadIdx.x;
    if (e < E4) {
        int4 s = __ldg(&src4[e]);
        int4 d = __ldg(&dst4[e]);
        float vx = __half2float(g_hhnh[s.x]);
        float vy = __half2float(g_hhnh[s.y]);
        float vz = __half2float(g_hhnh[s.z]);
        float vw = __half2float(g_hhnh[s.w]);
        if ((unsigned)d.x < (unsigned)NN) atomicAdd(&g_s2[d.x], vx);
        if ((unsigned)d.y < (unsigned)NN) atomicAdd(&g_s2[d.y], vy);
        if ((unsigned)d.z < (unsigned)NN) atomicAdd(&g_s2[d.z], vz);
        if ((unsigned)d.w < (unsigned)NN) atomicAdd(&g_s2[d.w], vw);
    }
}

// ---------------- GEMV: 2 rows per block, v4 shared across rows ----------------
__global__ void k_gemv(const float* __restrict__ Wf1,
                       const float* __restrict__ bf1) {
    const int r0 = blockIdx.x * 2;
    const int tid = threadIdx.x;
    const float4* __restrict__ rowA = (const float4*)(Wf1 + (size_t)r0 * NN);
    const float4* __restrict__ rowB = (const float4*)(Wf1 + (size_t)(r0 + 1) * NN);
    const float4* __restrict__ vv   = (const float4*)g_v;
    const int n4 = NN / 4;                 // 25000
    const int nfull = (n4 / 512) * 512;    // 24576

    float a0 = 0.f, a1 = 0.f, b0 = 0.f, b1 = 0.f;
    for (int i = tid; i < nfull; i += 512) {
        float4 x0 = vv[i];
        float4 x1 = vv[i + 256];
        float4 wA0 = __ldg(&rowA[i]);
        float4 wA1 = __ldg(&rowA[i + 256]);
        float4 wB0 = __ldg(&rowB[i]);
        float4 wB1 = __ldg(&rowB[i + 256]);
        a0 += wA0.x*x0.x + wA0.y*x0.y + wA0.z*x0.z + wA0.w*x0.w;
        a1 += wA1.x*x1.x + wA1.y*x1.y + wA1.z*x1.z + wA1.w*x1.w;
        b0 += wB0.x*x0.x + wB0.y*x0.y + wB0.z*x0.z + wB0.w*x0.w;
        b1 += wB1.x*x1.x + wB1.y*x1.y + wB1.z*x1.z + wB1.w*x1.w;
    }
    for (int i = nfull + tid; i < n4; i += 256) {
        float4 x = vv[i];
        float4 wA = __ldg(&rowA[i]);
        float4 wB = __ldg(&rowB[i]);
        a0 += wA.x*x.x + wA.y*x.y + wA.z*x.z + wA.w*x.w;
        b0 += wB.x*x.x + wB.y*x.y + wB.z*x.z + wB.w*x.w;
    }
    float sa = a0 + a1;
    float sb = b0 + b1;

#pragma unroll
    for (int o = 16; o > 0; o >>= 1) {
        sa += __shfl_down_sync(0xFFFFFFFFu, sa, o);
        sb += __shfl_down_sync(0xFFFFFFFFu, sb, o);
    }
    __shared__ float redA[8], redB[8];
    int lane = tid & 31, wid = tid >> 5;
    if (lane == 0) { redA[wid] = sa; redB[wid] = sb; }
    __syncthreads();
    if (wid == 0) {
        sa = (lane < 8) ? redA[lane] : 0.0f;
        sb = (lane < 8) ? redB[lane] : 0.0f;
#pragma unroll
        for (int o = 4; o > 0; o >>= 1) {
            sa += __shfl_down_sync(0xFFFFFFFFu, sa, o);
            sb += __shfl_down_sync(0xFFFFFFFFu, sb, o);
        }
        if (lane == 0) {
            g_z[r0]     = lrelu(sa + __ldg(&bf1[r0]));
            g_z[r0 + 1] = lrelu(sb + __ldg(&bf1[r0 + 1]));
        }
    }
}

// ---------------- FC2: one block per output row ----------------
__global__ void k_fc2(const float* __restrict__ Wf2,
                      const float* __restrict__ bf2) {
    const int o = blockIdx.x;          // 0..255
    const int tid = threadIdx.x;       // 128 threads
    const float4* __restrict__ row = (const float4*)(Wf2 + (size_t)o * HIDD);
    const float4* __restrict__ zz  = (const float4*)g_z;
    float s = 0.0f;
#pragma unroll
    for (int i = tid; i < HIDD / 4; i += 128) {   // 2 iterations
        float4 w = __ldg(&row[i]);
        float4 z = zz[i];
        s += w.x*z.x + w.y*z.y + w.z*z.z + w.w*z.w;
    }
#pragma unroll
    for (int off = 16; off > 0; off >>= 1)
        s += __shfl_down_sync(0xFFFFFFFFu, s, off);
    __shared__ float red[4];
    int lane = tid & 31, wid = tid >> 5;
    if (lane == 0) red[wid] = s;
    __syncthreads();
    if (tid == 0) {
        float t = red[0] + red[1] + red[2] + red[3];
        g_logits[o] = t + __ldg(&bf2[o]);
    }
}

// ---------------- log_softmax over 256 logits ----------------
__global__ void k_logsoftmax(float* __restrict__ out) {
    __shared__ float red[OUTD];
    const int t = threadIdx.x;
    float s = g_logits[t];

    red[t] = s;
    __syncthreads();
#pragma unroll
    for (int o = OUTD / 2; o > 0; o >>= 1) {
        if (t < o) red[t] = fmaxf(red[t], red[t + o]);
        __syncthreads();
    }
    float mx = red[0];
    __syncthreads();

    red[t] = expf(s - mx);
    __syncthreads();
#pragma unroll
    for (int o = OUTD / 2; o > 0; o >>= 1) {
        if (t < o) red[t] += red[t + o];
        __syncthreads();
    }
    float lse = mx + logf(red[0]);
    out[t] = s - lse;
}

// ---------------- launch ----------------
extern "C" void kernel_launch(void* const* d_in, const int* in_sizes, int n_in,
                              void* d_out, int out_size) {
    const float* x   = (const float*)d_in[0];
    const int*   ei  = (const int*)d_in[1];     // int32 (jax downcast)
    const float* W1c = (const float*)d_in[2];
    const float* b1c = (const float*)d_in[3];
    const float* W2c = (const float*)d_in[4];
    const float* b2c = (const float*)d_in[5];
    const float* Wf1 = (const float*)d_in[6];
    const float* bf1 = (const float*)d_in[7];
    const float* Wf2 = (const float*)d_in[8];
    const float* bf2 = (const float*)d_in[9];
    float* out = (float*)d_out;

    const int E = in_sizes[1] / 2;              // 3,200,000
    const int E4 = E / 4;                       // 800,000
    const int4* src4 = (const int4*)ei;
    const int4* dst4 = (const int4*)(ei + E);

    const int TB = 256;
    const int nb_node  = (NN + TB - 1) / TB;
    const int nb_edge4 = (E4 + TB - 1) / TB;

    // zero degrees via captured memset (no kernel launch)
    void* degp = nullptr;
    cudaGetSymbolAddress(&degp, g_degf);
    cudaMemsetAsync(degp, 0, NN * sizeof(float));

    k_deg<<<nb_edge4, TB>>>(dst4, E4);
    k_node1<<<nb_node, TB>>>(x);
    k_scatter1<<<nb_edge4, TB>>>(src4, dst4, E4);
    k_node2<<<nb_node, TB>>>(W1c, b1c, W2c);
    k_scatter2<<<nb_edge4, TB>>>(src4, dst4, E4);
    k_node3<<<nb_node, TB>>>(b2c);
    k_gemv<<<HIDD / 2, TB>>>(Wf1, bf1);
    k_fc2<<<OUTD, 128>>>(Wf2, bf2);
    k_logsoftmax<<<1, OUTD>>>(out);
}

// round 8
// speedup vs baseline: 1.9191x; 1.0553x over previous
#include <cuda_runtime.h>
#include <cuda_fp16.h>
#include <math.h>

#define NN   100000
#define CONV 16
#define HIDD 1024
#define OUTD 256

// ---------------- device scratch (no allocations allowed) ----------------
__device__ float  g_degf[NN];
__device__ float  g_dinv[NN];
__device__ float  g_s1[NN];      // conv1 accumulator (fp32 atomics)
__device__ __half g_xnh[NN];     // x[i]*dinv[i] as fp16 (L1-resident gather array)
__device__ float  g_s2[NN];      // conv2 accumulator
__device__ __half g_hhnh[NN];    // hh[i]*dinv[i] as fp16
__device__ float  g_v[NN];       // final node scalar
__device__ float  g_z[HIDD];     // hidden layer (post-lrelu)
__device__ float  g_logits[OUTD];

__device__ __forceinline__ float lrelu(float x) {
    return x >= 0.0f ? x : 0.01f * x;
}

// streaming (evict-first) int4 load — keeps L1 free for gather arrays
__device__ __forceinline__ int4 ldcs4(const int4* p) {
    return __ldcs(p);
}

// ---------------- node kernels ----------------
__global__ void k_node1(const float* __restrict__ x) {
    int i = blockIdx.x * blockDim.x + threadIdx.x;
    if (i < NN) {
        float dinv = rsqrtf(g_degf[i] + 1.0f);  // +1 = self-loop
        g_dinv[i] = dinv;
        float xn = x[i] * dinv;
        g_xnh[i] = __float2half(xn);
        g_s1[i] = xn * dinv;   // self-loop contribution (fp32, exact)
    }
}

__global__ void k_node2(const float* __restrict__ W1c,
                        const float* __restrict__ b1c,
                        const float* __restrict__ W2c) {
    int i = blockIdx.x * blockDim.x + threadIdx.x;
    if (i < NN) {
        float dinv = g_dinv[i];
        float a = dinv * g_s1[i];
        float hh = 0.0f;
#pragma unroll
        for (int c = 0; c < CONV; c++) {
            float t = fmaf(a, __ldg(&W1c[c]), __ldg(&b1c[c]));
            t = lrelu(t);
            hh = fmaf(t, __ldg(&W2c[c]), hh);
        }
        float hn = hh * dinv;
        g_hhnh[i] = __float2half(hn);
        g_s2[i] = hn * dinv;   // self-loop contribution (fp32)
    }
}

__global__ void k_node3(const float* __restrict__ b2c) {
    int i = blockIdx.x * blockDim.x + threadIdx.x;
    if (i < NN) {
        float t = g_dinv[i] * g_s2[i] + __ldg(&b2c[0]);
        g_v[i] = lrelu(t);
    }
}

// ---------------- edge kernels: 4 edges per thread via int4 ----------------
__global__ void k_deg(const int4* __restrict__ dst4, int E4) {
    int e = blockIdx.x * blockDim.x + threadIdx.x;
    if (e < E4) {
        int4 d = ldcs4(&dst4[e]);
        if ((unsigned)d.x < (unsigned)NN) atomicAdd(&g_degf[d.x], 1.0f);
        if ((unsigned)d.y < (unsigned)NN) atomicAdd(&g_degf[d.y], 1.0f);
        if ((unsigned)d.z < (unsigned)NN) atomicAdd(&g_degf[d.z], 1.0f);
        if ((unsigned)d.w < (unsigned)NN) atomicAdd(&g_degf[d.w], 1.0f);
    }
}

__global__ void k_scatter1(const int4* __restrict__ src4,
                           const int4* __restrict__ dst4, int E4) {
    int e = blockIdx.x * blockDim.x + threadIdx.x;
    if (e < E4) {
        int4 s = ldcs4(&src4[e]);
        int4 d = ldcs4(&dst4[e]);
        float vx = __half2float(g_xnh[s.x]);
        float vy = __half2float(g_xnh[s.y]);
        float vz = __half2float(g_xnh[s.z]);
        float vw = __half2float(g_xnh[s.w]);
        if ((unsigned)d.x < (unsigned)NN) atomicAdd(&g_s1[d.x], vx);
        if ((unsigned)d.y < (unsigned)NN) atomicAdd(&g_s1[d.y], vy);
        if ((unsigned)d.z < (unsigned)NN) atomicAdd(&g_s1[d.z], vz);
        if ((unsigned)d.w < (unsigned)NN) atomicAdd(&g_s1[d.w], vw);
    }
}

__global__ void k_scatter2(const int4* __restrict__ src4,
                           const int4* __restrict__ dst4, int E4) {
    int e = blockIdx.x * blockDim.x + threadIdx.x;
    if (e < E4) {
        int4 s = ldcs4(&src4[e]);
        int4 d = ldcs4(&dst4[e]);
        float vx = __half2float(g_hhnh[s.x]);
        float vy = __half2float(g_hhnh[s.y]);
        float vz = __half2float(g_hhnh[s.z]);
        float vw = __half2float(g_hhnh[s.w]);
        if ((unsigned)d.x < (unsigned)NN) atomicAdd(&g_s2[d.x], vx);
        if ((unsigned)d.y < (unsigned)NN) atomicAdd(&g_s2[d.y], vy);
        if ((unsigned)d.z < (unsigned)NN) atomicAdd(&g_s2[d.z], vz);
        if ((unsigned)d.w < (unsigned)NN) atomicAdd(&g_s2[d.w], vw);
    }
}

// ---------------- GEMV: 4 rows per block, 512 threads ----------------
// z[h] = lrelu(dot(Wf1[h,:], v) + bf1[h]). Wf1 streamed (read-once), v cached.
__global__ void k_gemv(const float* __restrict__ Wf1,
                       const float* __restrict__ bf1) {
    const int r0 = blockIdx.x * 4;
    const int tid = threadIdx.x;     // 512 threads
    const float4* __restrict__ rowA = (const float4*)(Wf1 + (size_t)(r0 + 0) * NN);
    const float4* __restrict__ rowB = (const float4*)(Wf1 + (size_t)(r0 + 1) * NN);
    const float4* __restrict__ rowC = (const float4*)(Wf1 + (size_t)(r0 + 2) * NN);
    const float4* __restrict__ rowD = (const float4*)(Wf1 + (size_t)(r0 + 3) * NN);
    const float4* __restrict__ vv   = (const float4*)g_v;
    const int n4 = NN / 4;           // 25000

    float sa = 0.f, sb = 0.f, sc = 0.f, sd = 0.f;
    for (int i = tid; i < n4; i += 512) {
        float4 x  = vv[i];
        float4 wA = __ldcs(&rowA[i]);
        float4 wB = __ldcs(&rowB[i]);
        float4 wC = __ldcs(&rowC[i]);
        float4 wD = __ldcs(&rowD[i]);
        sa += wA.x*x.x + wA.y*x.y + wA.z*x.z + wA.w*x.w;
        sb += wB.x*x.x + wB.y*x.y + wB.z*x.z + wB.w*x.w;
        sc += wC.x*x.x + wC.y*x.y + wC.z*x.z + wC.w*x.w;
        sd += wD.x*x.x + wD.y*x.y + wD.z*x.z + wD.w*x.w;
    }

#pragma unroll
    for (int o = 16; o > 0; o >>= 1) {
        sa += __shfl_down_sync(0xFFFFFFFFu, sa, o);
        sb += __shfl_down_sync(0xFFFFFFFFu, sb, o);
        sc += __shfl_down_sync(0xFFFFFFFFu, sc, o);
        sd += __shfl_down_sync(0xFFFFFFFFu, sd, o);
    }
    __shared__ float redA[16], redB[16], redC[16], redD[16];
    int lane = tid & 31, wid = tid >> 5;   // 16 warps
    if (lane == 0) { redA[wid] = sa; redB[wid] = sb; redC[wid] = sc; redD[wid] = sd; }
    __syncthreads();
    if (wid == 0) {
        sa = (lane < 16) ? redA[lane] : 0.0f;
        sb = (lane < 16) ? redB[lane] : 0.0f;
        sc = (lane < 16) ? redC[lane] : 0.0f;
        sd = (lane < 16) ? redD[lane] : 0.0f;
#pragma unroll
        for (int o = 8; o > 0; o >>= 1) {
            sa += __shfl_down_sync(0xFFFFFFFFu, sa, o);
            sb += __shfl_down_sync(0xFFFFFFFFu, sb, o);
            sc += __shfl_down_sync(0xFFFFFFFFu, sc, o);
            sd += __shfl_down_sync(0xFFFFFFFFu, sd, o);
        }
        if (lane == 0) {
            g_z[r0 + 0] = lrelu(sa + __ldg(&bf1[r0 + 0]));
            g_z[r0 + 1] = lrelu(sb + __ldg(&bf1[r0 + 1]));
            g_z[r0 + 2] = lrelu(sc + __ldg(&bf1[r0 + 2]));
            g_z[r0 + 3] = lrelu(sd + __ldg(&bf1[r0 + 3]));
        }
    }
}

// ---------------- FC2: one block per output row ----------------
__global__ void k_fc2(const float* __restrict__ Wf2,
                      const float* __restrict__ bf2) {
    const int o = blockIdx.x;          // 0..255
    const int tid = threadIdx.x;       // 128 threads
    const float4* __restrict__ row = (const float4*)(Wf2 + (size_t)o * HIDD);
    const float4* __restrict__ zz  = (const float4*)g_z;
    float s = 0.0f;
#pragma unroll
    for (int i = tid; i < HIDD / 4; i += 128) {   // 2 iterations
        float4 w = __ldg(&row[i]);
        float4 z = zz[i];
        s += w.x*z.x + w.y*z.y + w.z*z.z + w.w*z.w;
    }
#pragma unroll
    for (int off = 16; off > 0; off >>= 1)
        s += __shfl_down_sync(0xFFFFFFFFu, s, off);
    __shared__ float red[4];
    int lane = tid & 31, wid = tid >> 5;
    if (lane == 0) red[wid] = s;
    __syncthreads();
    if (tid == 0) {
        float t = red[0] + red[1] + red[2] + red[3];
        g_logits[o] = t + __ldg(&bf2[o]);
    }
}

// ---------------- log_softmax over 256 logits ----------------
__global__ void k_logsoftmax(float* __restrict__ out) {
    __shared__ float red[OUTD];
    const int t = threadIdx.x;
    float s = g_logits[t];

    red[t] = s;
    __syncthreads();
#pragma unroll
    for (int o = OUTD / 2; o > 0; o >>= 1) {
        if (t < o) red[t] = fmaxf(red[t], red[t + o]);
        __syncthreads();
    }
    float mx = red[0];
    __syncthreads();

    red[t] = expf(s - mx);
    __syncthreads();
#pragma unroll
    for (int o = OUTD / 2; o > 0; o >>= 1) {
        if (t < o) red[t] += red[t + o];
        __syncthreads();
    }
    float lse = mx + logf(red[0]);
    out[t] = s - lse;
}

// ---------------- launch ----------------
extern "C" void kernel_launch(void* const* d_in, const int* in_sizes, int n_in,
                              void* d_out, int out_size) {
    const float* x   = (const float*)d_in[0];
    const int*   ei  = (const int*)d_in[1];     // int32 (jax downcast)
    const float* W1c = (const float*)d_in[2];
    const float* b1c = (const float*)d_in[3];
    const float* W2c = (const float*)d_in[4];
    const float* b2c = (const float*)d_in[5];
    const float* Wf1 = (const float*)d_in[6];
    const float* bf1 = (const float*)d_in[7];
    const float* Wf2 = (const float*)d_in[8];
    const float* bf2 = (const float*)d_in[9];
    float* out = (float*)d_out;

    const int E = in_sizes[1] / 2;              // 3,200,000
    const int E4 = E / 4;                       // 800,000
    const int4* src4 = (const int4*)ei;
    const int4* dst4 = (const int4*)(ei + E);

    const int TB = 256;
    const int nb_node  = (NN + TB - 1) / TB;
    const int nb_edge4 = (E4 + TB - 1) / TB;

    // zero degrees via captured memset (no kernel launch)
    void* degp = nullptr;
    cudaGetSymbolAddress(&degp, g_degf);
    cudaMemsetAsync(degp, 0, NN * sizeof(float));

    k_deg<<<nb_edge4, TB>>>(dst4, E4);
    k_node1<<<nb_node, TB>>>(x);
    k_scatter1<<<nb_edge4, TB>>>(src4, dst4, E4);
    k_node2<<<nb_node, TB>>>(W1c, b1c, W2c);
    k_scatter2<<<nb_edge4, TB>>>(src4, dst4, E4);
    k_node3<<<nb_node, TB>>>(b2c);
    k_gemv<<<HIDD / 4, 512>>>(Wf1, bf1);
    k_fc2<<<OUTD, 128>>>(Wf2, bf2);
    k_logsoftmax<<<1, OUTD>>>(out);
}

// round 10
// speedup vs baseline: 1.9401x; 1.0110x over previous
#include <cuda_runtime.h>
#include <cuda_fp16.h>
#include <math.h>

#define NN   100000
#define NN4  (NN / 4)        // 25000
#define CONV 16
#define HIDD 1024
#define OUTD 256

// ---------------- device scratch (no allocations allowed) ----------------
__device__ __align__(16) float  g_degf[NN];
__device__ __align__(16) float  g_dinv[NN];
__device__ __align__(16) float  g_s1[NN];      // conv1 accumulator (fp32 atomics)
__device__ __align__(16) __half g_xnh[NN];     // x[i]*dinv[i] as fp16 (L1-resident gathers)
__device__ __align__(16) float  g_s2[NN];      // conv2 accumulator
__device__ __align__(16) __half g_hhnh[NN];    // hh[i]*dinv[i] as fp16
__device__ __align__(16) float  g_v[NN];       // final node scalar
__device__ __align__(16) float  g_z[HIDD];     // hidden layer (post-lrelu)
__device__ __align__(16) float  g_logits[OUTD];
__device__ unsigned g_fc2cnt;                  // reset each run in node3

__device__ __forceinline__ float lrelu(float x) {
    return x >= 0.0f ? x : 0.01f * x;
}

__device__ __forceinline__ unsigned h2_as_u32(__half2 h) {
    return *reinterpret_cast<unsigned*>(&h);
}

// ---------------- node kernels (4 nodes per thread) ----------------
__global__ void k_node1(const float4* __restrict__ x4) {
    int i = blockIdx.x * blockDim.x + threadIdx.x;
    if (i < NN4) {
        float4 dg = ((const float4*)g_degf)[i];
        float4 xv = __ldg(&x4[i]);
        float d0 = rsqrtf(dg.x + 1.0f);
        float d1 = rsqrtf(dg.y + 1.0f);
        float d2 = rsqrtf(dg.z + 1.0f);
        float d3 = rsqrtf(dg.w + 1.0f);
        ((float4*)g_dinv)[i] = make_float4(d0, d1, d2, d3);
        float xn0 = xv.x * d0, xn1 = xv.y * d1, xn2 = xv.z * d2, xn3 = xv.w * d3;
        __half2 h01 = __floats2half2_rn(xn0, xn1);
        __half2 h23 = __floats2half2_rn(xn2, xn3);
        ((uint2*)g_xnh)[i] = make_uint2(h2_as_u32(h01), h2_as_u32(h23));
        ((float4*)g_s1)[i] = make_float4(xn0 * d0, xn1 * d1, xn2 * d2, xn3 * d3);
    }
}

__global__ void k_node2(const float* __restrict__ W1c,
                        const float* __restrict__ b1c,
                        const float* __restrict__ W2c) {
    int i = blockIdx.x * blockDim.x + threadIdx.x;
    if (i < NN4) {
        float4 dv = ((const float4*)g_dinv)[i];
        float4 s1 = ((const float4*)g_s1)[i];
        float a[4] = { dv.x * s1.x, dv.y * s1.y, dv.z * s1.z, dv.w * s1.w };
        float hh[4] = { 0.f, 0.f, 0.f, 0.f };
#pragma unroll
        for (int c = 0; c < CONV; c++) {
            float w1 = __ldg(&W1c[c]);
            float bb = __ldg(&b1c[c]);
            float w2 = __ldg(&W2c[c]);
#pragma unroll
            for (int j = 0; j < 4; j++) {
                float t = lrelu(fmaf(a[j], w1, bb));
                hh[j] = fmaf(t, w2, hh[j]);
            }
        }
        float hn0 = hh[0] * dv.x, hn1 = hh[1] * dv.y;
        float hn2 = hh[2] * dv.z, hn3 = hh[3] * dv.w;
        __half2 h01 = __floats2half2_rn(hn0, hn1);
        __half2 h23 = __floats2half2_rn(hn2, hn3);
        ((uint2*)g_hhnh)[i] = make_uint2(h2_as_u32(h01), h2_as_u32(h23));
        ((float4*)g_s2)[i] = make_float4(hn0 * dv.x, hn1 * dv.y, hn2 * dv.z, hn3 * dv.w);
    }
}

__global__ void k_node3(const float* __restrict__ b2c) {
    int i = blockIdx.x * blockDim.x + threadIdx.x;
    if (i == 0) g_fc2cnt = 0;   // reset fc2 completion counter each run
    if (i < NN4) {
        float b = __ldg(&b2c[0]);
        float4 dv = ((const float4*)g_dinv)[i];
        float4 s2 = ((const float4*)g_s2)[i];
        ((float4*)g_v)[i] = make_float4(
            lrelu(fmaf(dv.x, s2.x, b)),
            lrelu(fmaf(dv.y, s2.y, b)),
            lrelu(fmaf(dv.z, s2.z, b)),
            lrelu(fmaf(dv.w, s2.w, b)));
    }
}

// ---------------- edge kernels: 4 edges per thread via int4 ----------------
__global__ void k_deg(const int4* __restrict__ dst4, int E4) {
    int e = blockIdx.x * blockDim.x + threadIdx.x;
    if (e < E4) {
        int4 d = __ldcs(&dst4[e]);
        if ((unsigned)d.x < (unsigned)NN) atomicAdd(&g_degf[d.x], 1.0f);
        if ((unsigned)d.y < (unsigned)NN) atomicAdd(&g_degf[d.y], 1.0f);
        if ((unsigned)d.z < (unsigned)NN) atomicAdd(&g_degf[d.z], 1.0f);
        if ((unsigned)d.w < (unsigned)NN) atomicAdd(&g_degf[d.w], 1.0f);
    }
}

__global__ void k_scatter1(const int4* __restrict__ src4,
                           const int4* __restrict__ dst4, int E4) {
    int e = blockIdx.x * blockDim.x + threadIdx.x;
    if (e < E4) {
        int4 s = __ldcs(&src4[e]);
        int4 d = __ldcs(&dst4[e]);
        float vx = __half2float(g_xnh[s.x]);
        float vy = __half2float(g_xnh[s.y]);
        float vz = __half2float(g_xnh[s.z]);
        float vw = __half2float(g_xnh[s.w]);
        if ((unsigned)d.x < (unsigned)NN) atomicAdd(&g_s1[d.x], vx);
        if ((unsigned)d.y < (unsigned)NN) atomicAdd(&g_s1[d.y], vy);
        if ((unsigned)d.z < (unsigned)NN) atomicAdd(&g_s1[d.z], vz);
        if ((unsigned)d.w < (unsigned)NN) atomicAdd(&g_s1[d.w], vw);
    }
}

__global__ void k_scatter2(const int4* __restrict__ src4,
                           const int4* __restrict__ dst4, int E4) {
    int e = blockIdx.x * blockDim.x + threadIdx.x;
    if (e < E4) {
        int4 s = __ldcs(&src4[e]);
        int4 d = __ldcs(&dst4[e]);
        float vx = __half2float(g_hhnh[s.x]);
        float vy = __half2float(g_hhnh[s.y]);
        float vz = __half2float(g_hhnh[s.z]);
        float vw = __half2float(g_hhnh[s.w]);
        if ((unsigned)d.x < (unsigned)NN) atomicAdd(&g_s2[d.x], vx);
        if ((unsigned)d.y < (unsigned)NN) atomicAdd(&g_s2[d.y], vy);
        if ((unsigned)d.z < (unsigned)NN) atomicAdd(&g_s2[d.z], vz);
        if ((unsigned)d.w < (unsigned)NN) atomicAdd(&g_s2[d.w], vw);
    }
}

// ---------------- GEMV: 4 rows per block, 512 threads ----------------
__global__ void k_gemv(const float* __restrict__ Wf1,
                       const float* __restrict__ bf1) {
    const int r0 = blockIdx.x * 4;
    const int tid = threadIdx.x;     // 512 threads
    const float4* __restrict__ rowA = (const float4*)(Wf1 + (size_t)(r0 + 0) * NN);
    const float4* __restrict__ rowB = (const float4*)(Wf1 + (size_t)(r0 + 1) * NN);
    const float4* __restrict__ rowC = (const float4*)(Wf1 + (size_t)(r0 + 2) * NN);
    const float4* __restrict__ rowD = (const float4*)(Wf1 + (size_t)(r0 + 3) * NN);
    const float4* __restrict__ vv   = (const float4*)g_v;

    float sa = 0.f, sb = 0.f, sc = 0.f, sd = 0.f;
    for (int i = tid; i < NN4; i += 512) {
        float4 x  = vv[i];
        float4 wA = __ldcs(&rowA[i]);
        float4 wB = __ldcs(&rowB[i]);
        float4 wC = __ldcs(&rowC[i]);
        float4 wD = __ldcs(&rowD[i]);
        sa += wA.x*x.x + wA.y*x.y + wA.z*x.z + wA.w*x.w;
        sb += wB.x*x.x + wB.y*x.y + wB.z*x.z + wB.w*x.w;
        sc += wC.x*x.x + wC.y*x.y + wC.z*x.z + wC.w*x.w;
        sd += wD.x*x.x + wD.y*x.y + wD.z*x.z + wD.w*x.w;
    }

#pragma unroll
    for (int o = 16; o > 0; o >>= 1) {
        sa += __shfl_down_sync(0xFFFFFFFFu, sa, o);
        sb += __shfl_down_sync(0xFFFFFFFFu, sb, o);
        sc += __shfl_down_sync(0xFFFFFFFFu, sc, o);
        sd += __shfl_down_sync(0xFFFFFFFFu, sd, o);
    }
    __shared__ float redA[16], redB[16], redC[16], redD[16];
    int lane = tid & 31, wid = tid >> 5;   // 16 warps
    if (lane == 0) { redA[wid] = sa; redB[wid] = sb; redC[wid] = sc; redD[wid] = sd; }
    __syncthreads();
    if (wid == 0) {
        sa = (lane < 16) ? redA[lane] : 0.0f;
        sb = (lane < 16) ? redB[lane] : 0.0f;
        sc = (lane < 16) ? redC[lane] : 0.0f;
        sd = (lane < 16) ? redD[lane] : 0.0f;
#pragma unroll
        for (int o = 8; o > 0; o >>= 1) {
            sa += __shfl_down_sync(0xFFFFFFFFu, sa, o);
            sb += __shfl_down_sync(0xFFFFFFFFu, sb, o);
            sc += __shfl_down_sync(0xFFFFFFFFu, sc, o);
            sd += __shfl_down_sync(0xFFFFFFFFu, sd, o);
        }
        if (lane == 0) {
            g_z[r0 + 0] = lrelu(sa + __ldg(&bf1[r0 + 0]));
            g_z[r0 + 1] = lrelu(sb + __ldg(&bf1[r0 + 1]));
            g_z[r0 + 2] = lrelu(sc + __ldg(&bf1[r0 + 2]));
            g_z[r0 + 3] = lrelu(sd + __ldg(&bf1[r0 + 3]));
        }
    }
}

// ---------------- FC2 + fused log_softmax (last-block completes) ----------------
__global__ void k_fc2(const float* __restrict__ Wf2,
                      const float* __restrict__ bf2,
                      float* __restrict__ out) {
    const int o = blockIdx.x;          // 0..255
    const int tid = threadIdx.x;       // 128 threads
    const float4* __restrict__ row = (const float4*)(Wf2 + (size_t)o * HIDD);
    const float4* __restrict__ zz  = (const float4*)g_z;
    float s = 0.0f;
#pragma unroll
    for (int i = tid; i < HIDD / 4; i += 128) {   // 2 iterations
        float4 w = __ldg(&row[i]);
        float4 z = zz[i];
        s += w.x*z.x + w.y*z.y + w.z*z.z + w.w*z.w;
    }
#pragma unroll
    for (int off = 16; off > 0; off >>= 1)
        s += __shfl_down_sync(0xFFFFFFFFu, s, off);
    __shared__ float red[4];
    int lane = tid & 31, wid = tid >> 5;
    if (lane == 0) red[wid] = s;
    __syncthreads();
    __shared__ bool last;
    if (tid == 0) {
        float t = red[0] + red[1] + red[2] + red[3];
        g_logits[o] = t + __ldg(&bf2[o]);
        __threadfence();
        unsigned done = atomicAdd(&g_fc2cnt, 1u);
        last = (done == (unsigned)(gridDim.x - 1));
    }
    __syncthreads();
    if (!last) return;

    // ---- last block: log_softmax over 256 logits with 128 threads ----
    __shared__ float buf[128];
    float a0 = g_logits[tid];
    float a1 = g_logits[tid + 128];
    float m = fmaxf(a0, a1);
    buf[tid] = m;
    __syncthreads();
#pragma unroll
    for (int off = 64; off > 0; off >>= 1) {
        if (tid < off) buf[tid] = fmaxf(buf[tid], buf[tid + off]);
        __syncthreads();
    }
    float mx = buf[0];
    __syncthreads();
    buf[tid] = expf(a0 - mx) + expf(a1 - mx);
    __syncthreads();
#pragma unroll
    for (int off = 64; off > 0; off >>= 1) {
        if (tid < off) buf[tid] += buf[tid + off];
        __syncthreads();
    }
    float lse = mx + logf(buf[0]);
    out[tid]       = a0 - lse;
    out[tid + 128] = a1 - lse;
}

// ---------------- launch ----------------
extern "C" void kernel_launch(void* const* d_in, const int* in_sizes, int n_in,
                              void* d_out, int out_size) {
    const float* x   = (const float*)d_in[0];
    const int*   ei  = (const int*)d_in[1];     // int32 (jax downcast)
    const float* W1c = (const float*)d_in[2];
    const float* b1c = (const float*)d_in[3];
    const float* W2c = (const float*)d_in[4];
    const float* b2c = (const float*)d_in[5];
    const float* Wf1 = (const float*)d_in[6];
    const float* bf1 = (const float*)d_in[7];
    const float* Wf2 = (const float*)d_in[8];
    const float* bf2 = (const float*)d_in[9];
    float* out = (float*)d_out;

    const int E = in_sizes[1] / 2;              // 3,200,000
    const int E4 = E / 4;                       // 800,000
    const int4* src4 = (const int4*)ei;
    const int4* dst4 = (const int4*)(ei + E);

    const int TB = 256;
    const int nb_node4 = (NN4 + TB - 1) / TB;   // 98
    const int nb_edge4 = (E4 + TB - 1) / TB;

    // zero degrees via captured memset (no kernel launch)
    void* degp = nullptr;
    cudaGetSymbolAddress(&degp, g_degf);
    cudaMemsetAsync(degp, 0, NN * sizeof(float));

    k_deg<<<nb_edge4, TB>>>(dst4, E4);
    k_node1<<<nb_node4, TB>>>((const float4*)x);
    k_scatter1<<<nb_edge4, TB>>>(src4, dst4, E4);
    k_node2<<<nb_node4, TB>>>(W1c, b1c, W2c);
    k_scatter2<<<nb_edge4, TB>>>(src4, dst4, E4);
    k_node3<<<nb_node4, TB>>>(b2c);
    k_gemv<<<HIDD / 4, 512>>>(Wf1, bf1);
    k_fc2<<<OUTD, 128>>>(Wf2, bf2, out);
}